// round 11
// baseline (speedup 1.0000x reference)
#include <cuda_runtime.h>
#include <cuda_bf16.h>
#include <cuda_fp16.h>
#include <cstdint>
#include <cstddef>

#define N_NODES 100000
#define N_EDGES 1600000
#define HIDC    128
#define N_TRUCK 32

// ---------------- device scratch ------------------------------------------
__device__ float         g_F   [(size_t)N_NODES * HIDC];     // head1 -> head2 only
__device__ __half        g_hx  [(size_t)N_NODES * HIDC];
__device__ __half        g_hA  [(size_t)N_NODES * HIDC];
__device__ __half        g_hB  [(size_t)N_NODES * HIDC];
__device__ __nv_bfloat16 g_p0h [(size_t)N_NODES * HIDC];
__device__ __nv_bfloat16 g_p0l [(size_t)N_NODES * HIDC];
__device__ __nv_bfloat16 g_p1h [(size_t)N_NODES * HIDC];
__device__ __nv_bfloat16 g_p1l [(size_t)N_NODES * HIDC];
__device__ __nv_bfloat16 g_agh [(size_t)N_NODES * HIDC];
__device__ __nv_bfloat16 g_agl [(size_t)N_NODES * HIDC];
__device__ __nv_bfloat16 g_wtb [14 * 16384];
__device__ int   g_cnt[N_NODES];
__device__ int   g_cursor[N_NODES];
__device__ int   g_rowptr[N_NODES + 1];
__device__ int   g_srcsorted[N_EDGES];
__device__ int   g_blocksums[128];

// ---------------- helpers ---------------------------------------------------
__device__ __forceinline__ uint32_t smem_u32(const void* p) {
    uint32_t a;
    asm("{ .reg .u64 t; cvta.to.shared.u64 t, %1; cvt.u32.u64 %0, t; }" : "=r"(a) : "l"(p));
    return a;
}
__device__ __forceinline__ void split2(float a, float b, uint32_t& h, uint32_t& l) {
    __nv_bfloat162 hh = __floats2bfloat162_rn(a, b);
    __nv_bfloat162 ll = __floats2bfloat162_rn(a - __bfloat162float(hh.x),
                                              b - __bfloat162float(hh.y));
    h = *reinterpret_cast<uint32_t*>(&hh);
    l = *reinterpret_cast<uint32_t*>(&ll);
}
__device__ __forceinline__ void split4(float a, float b, float c, float d,
                                       uint32_t& h01, uint32_t& h23,
                                       uint32_t& l01, uint32_t& l23) {
    split2(a, b, h01, l01);
    split2(c, d, h23, l23);
}
__device__ __forceinline__ void ldm_x4(uint32_t& r0, uint32_t& r1, uint32_t& r2,
                                       uint32_t& r3, uint32_t addr) {
    asm volatile("ldmatrix.sync.aligned.m8n8.x4.shared.b16 {%0,%1,%2,%3}, [%4];"
                 : "=r"(r0), "=r"(r1), "=r"(r2), "=r"(r3) : "r"(addr));
}
__device__ __forceinline__ void mma16816(float* c, const uint32_t* a, const uint32_t* b) {
    asm volatile("mma.sync.aligned.m16n8k16.row.col.f32.bf16.bf16.f32 "
                 "{%0,%1,%2,%3}, {%4,%5,%6,%7}, {%8,%9}, {%0,%1,%2,%3};"
                 : "+f"(c[0]), "+f"(c[1]), "+f"(c[2]), "+f"(c[3])
                 : "r"(a[0]), "r"(a[1]), "r"(a[2]), "r"(a[3]), "r"(b[0]), "r"(b[1]));
}

// ---------------- CSR build ------------------------------------------------
__global__ void zero_cnt_kernel() {
    int i = blockIdx.x * blockDim.x + threadIdx.x;
    if (i < N_NODES) g_cnt[i] = 0;
}
__global__ void hist_kernel(const int* __restrict__ dst) {
    int i = blockIdx.x * blockDim.x + threadIdx.x;
    if (i < N_EDGES) atomicAdd(&g_cnt[dst[i]], 1);
}
__global__ void scan_phase1() {
    __shared__ int sh[1024];
    int i = blockIdx.x * 1024 + threadIdx.x;
    int v = (i < N_NODES) ? g_cnt[i] : 0;
    sh[threadIdx.x] = v;
    __syncthreads();
    for (int off = 1; off < 1024; off <<= 1) {
        int t = (threadIdx.x >= off) ? sh[threadIdx.x - off] : 0;
        __syncthreads();
        sh[threadIdx.x] += t;
        __syncthreads();
    }
    if (i < N_NODES) g_rowptr[i] = sh[threadIdx.x];
    if (threadIdx.x == 1023) g_blocksums[blockIdx.x] = sh[1023];
}
__global__ void scan_phase2(int nb) {
    __shared__ int sh[128];
    int t = threadIdx.x;
    int v = (t < nb) ? g_blocksums[t] : 0;
    sh[t] = v;
    __syncthreads();
    for (int off = 1; off < 128; off <<= 1) {
        int u = (t >= off) ? sh[t - off] : 0;
        __syncthreads();
        sh[t] += u;
        __syncthreads();
    }
    if (t < nb) g_blocksums[t] = sh[t] - v;   // exclusive
}
__global__ void scan_phase3() {
    int i = blockIdx.x * blockDim.x + threadIdx.x;
    if (i < N_NODES) {
        int excl = g_rowptr[i] - g_cnt[i] + g_blocksums[i >> 10];
        g_rowptr[i] = excl;
        g_cursor[i] = excl;
    }
    if (i == 0) g_rowptr[N_NODES] = N_EDGES;
}
__global__ void fill_kernel(const int* __restrict__ src, const int* __restrict__ dst) {
    int i = blockIdx.x * blockDim.x + threadIdx.x;
    if (i < N_EDGES) {
        int p = atomicAdd(&g_cursor[dst[i]], 1);
        g_srcsorted[p] = src[i];
    }
}

// ---------------- split x -> bf16 hi/lo pairs + fp16 copy -------------------
__global__ void split_kernel(const float* __restrict__ src,
                             __nv_bfloat16* __restrict__ hi,
                             __nv_bfloat16* __restrict__ lo,
                             __half* __restrict__ h16, int n4) {
    int i = blockIdx.x * blockDim.x + threadIdx.x;
    if (i >= n4) return;
    float4 v = __ldg((const float4*)src + i);
    uint32_t h01, h23, l01, l23;
    split4(v.x, v.y, v.z, v.w, h01, h23, l01, l23);
    *(uint2*)(hi + (size_t)i * 4) = make_uint2(h01, h23);
    *(uint2*)(lo + (size_t)i * 4) = make_uint2(l01, l23);
    __half2 p0 = __float22half2_rn(make_float2(v.x, v.y));
    __half2 p1 = __float22half2_rn(make_float2(v.z, v.w));
    *(uint2*)(h16 + (size_t)i * 4) =
        make_uint2(*reinterpret_cast<uint32_t*>(&p0), *reinterpret_cast<uint32_t*>(&p1));
}

// ---------------- weight prep: transpose + split ----------------------------
__global__ void wprep_kernel(const float* __restrict__ w0, const float* __restrict__ w1,
                             const float* __restrict__ w2, const float* __restrict__ w3,
                             const float* __restrict__ w4, const float* __restrict__ w5,
                             const float* __restrict__ w6) {
    int gid = blockIdx.x * blockDim.x + threadIdx.x;
    if (gid >= 7 * 16384) return;
    int m = gid >> 14;
    int r = gid & 16383;
    int n = r >> 7;
    int k = r & 127;
    const float* W = (m == 0) ? w0 : (m == 1) ? w1 : (m == 2) ? w2 : (m == 3) ? w3
                   : (m == 4) ? w4 : (m == 5) ? w5 : w6;
    float v = __ldg(W + k * 128 + n);
    __nv_bfloat16 h = __float2bfloat16(v);
    __nv_bfloat16 l = __float2bfloat16(v - __bfloat162float(h));
    int hidx = (m < 6) ? ((m >> 1) * 4 + (m & 1) * 2) : 12;
    g_wtb[(size_t)hidx * 16384 + n * 128 + k] = h;
    g_wtb[(size_t)(hidx + 1) * 16384 + n * 128 + k] = l;
}

// ---------------- aggregation: warp per node, fp16 gather, x2 unroll -------
__global__ void __launch_bounds__(256) agg_kernel(const __half* __restrict__ h,
                                                  __nv_bfloat16* __restrict__ ahi,
                                                  __nv_bfloat16* __restrict__ alo) {
    int gw   = (blockIdx.x * blockDim.x + threadIdx.x) >> 5;
    int lane = threadIdx.x & 31;
    if (gw >= N_NODES) return;
    int beg = g_rowptr[gw];
    int end = g_rowptr[gw + 1];
    float x0 = 0.f, x1 = 0.f, x2 = 0.f, x3 = 0.f;
    float y0 = 0.f, y1 = 0.f, y2 = 0.f, y3 = 0.f;
    int e = beg;
    for (; e + 2 <= end; e += 2) {
        int s0 = __ldg(g_srcsorted + e);
        int s1 = __ldg(g_srcsorted + e + 1);
        uint2 u0 = __ldg((const uint2*)(h + (size_t)s0 * HIDC + lane * 4));
        uint2 u1 = __ldg((const uint2*)(h + (size_t)s1 * HIDC + lane * 4));
        float2 f;
        f = __half22float2(*reinterpret_cast<__half2*>(&u0.x)); x0 += f.x; x1 += f.y;
        f = __half22float2(*reinterpret_cast<__half2*>(&u0.y)); x2 += f.x; x3 += f.y;
        f = __half22float2(*reinterpret_cast<__half2*>(&u1.x)); y0 += f.x; y1 += f.y;
        f = __half22float2(*reinterpret_cast<__half2*>(&u1.y)); y2 += f.x; y3 += f.y;
    }
    if (e < end) {
        int s0 = __ldg(g_srcsorted + e);
        uint2 u0 = __ldg((const uint2*)(h + (size_t)s0 * HIDC + lane * 4));
        float2 f;
        f = __half22float2(*reinterpret_cast<__half2*>(&u0.x)); x0 += f.x; x1 += f.y;
        f = __half22float2(*reinterpret_cast<__half2*>(&u0.y)); x2 += f.x; x3 += f.y;
    }
    x0 += y0; x1 += y1; x2 += y2; x3 += y3;
    uint32_t h01, h23, l01, l23;
    split4(x0, x1, x2, x3, h01, h23, l01, l23);
    size_t off = (size_t)gw * HIDC + lane * 4;
    *(uint2*)(ahi + off) = make_uint2(h01, h23);
    *(uint2*)(alo + off) = make_uint2(l01, l23);
}

// ---------------- mma.sync bf16x3 GEMM, 512 threads, KC=32, 2-stage --------
// out = act( [A1|A2] @ [B1;B2] + bias ); 4x4 warp grid, warp tile 32x32.
#define KC       32
#define PITCH    80                        // (32+8) halves * 2B; ldmatrix conflict-free
#define TILE_B   (128 * PITCH)             // 10240 B
#define STAGE_B  (4 * TILE_B)              // 40960 B
#define GEMM_SMEM (2 * STAGE_B)            // 81920 B

__global__ void __launch_bounds__(512, 1) gemm_mma(
    const __nv_bfloat16* __restrict__ a1h, const __nv_bfloat16* __restrict__ a1l,
    const __nv_bfloat16* __restrict__ a2h, const __nv_bfloat16* __restrict__ a2l,
    const __nv_bfloat16* __restrict__ b1h, const __nv_bfloat16* __restrict__ b1l,
    const __nv_bfloat16* __restrict__ b2h, const __nv_bfloat16* __restrict__ b2l,
    const float* __restrict__ bias,
    float* __restrict__ outf,
    __half* __restrict__ outh,
    __nv_bfloat16* __restrict__ outhi, __nv_bfloat16* __restrict__ outlo,
    int nc, int k1c)
{
    extern __shared__ char smem[];
    const uint32_t sbase = smem_u32(smem);
    const int tid  = threadIdx.x;
    const int wid  = tid >> 5;
    const int lane = tid & 31;
    const int wm = wid >> 2;            // 0..3 (32-row slab)
    const int wn = wid & 3;             // 0..3 (32-col slab)
    const int block_row = blockIdx.x * 128;

    float acc[2][4][4];
#pragma unroll
    for (int i = 0; i < 2; ++i)
#pragma unroll
        for (int j = 0; j < 4; ++j)
#pragma unroll
            for (int k = 0; k < 4; ++k) acc[i][j][k] = 0.f;

    auto pick = [&](int kc, const __nv_bfloat16*& ah, const __nv_bfloat16*& al,
                    const __nv_bfloat16*& bh, const __nv_bfloat16*& bl, int& acol) {
        if (kc < k1c) { ah = a1h; al = a1l; bh = b1h; bl = b1l; acol = kc * KC; }
        else          { ah = a2h; al = a2l; bh = b2h; bl = b2l; acol = (kc - k1c) * KC; }
    };

    const int lrow = tid >> 2;          // 0..127
    const int lq   = tid & 3;           // 0..3 (16B chunk within 64B row)
    auto ldg_chunk = [&](int kc, uint4* regs) {
        const __nv_bfloat16 *ah, *al, *bh, *bl; int acol;
        pick(kc, ah, al, bh, bl, acol);
#pragma unroll
        for (int t = 0; t < 4; ++t) {   // t = tile: 0 Ahi, 1 Alo, 2 Bhi, 3 Blo
            uint4 v = make_uint4(0, 0, 0, 0);
            if (t < 2) {
                int grow = block_row + lrow;
                if (grow < N_NODES) {
                    const __nv_bfloat16* src = (t == 0) ? ah : al;
                    v = *(const uint4*)(src + (size_t)grow * 128 + acol + lq * 8);
                }
            } else {
                const __nv_bfloat16* src = (t == 2) ? bh : bl;
                v = *(const uint4*)(src + (size_t)lrow * 128 + acol + lq * 8);
            }
            regs[t] = v;
        }
    };
    auto sts_chunk = [&](int stage, const uint4* regs) {
#pragma unroll
        for (int t = 0; t < 4; ++t)
            *(uint4*)(smem + stage * STAGE_B + t * TILE_B + lrow * PITCH + lq * 16) = regs[t];
    };

    const int r8  = lane & 7;
    const int sub = lane >> 3;
    auto compute_stage = [&](int stage) {
        const uint32_t so = sbase + stage * STAGE_B;
        const uint32_t Ah = so;
        const uint32_t Al = so + TILE_B;
        const uint32_t Bh = so + 2 * TILE_B;
        const uint32_t Bl = so + 3 * TILE_B;
#pragma unroll
        for (int ks = 0; ks < 2; ++ks) {
            uint32_t ah[2][4], al[2][4], bh[4][2], bl[4][2];
#pragma unroll
            for (int mi = 0; mi < 2; ++mi) {
                const int arow = wm * 32 + mi * 16 + r8 + (sub & 1) * 8;
                const uint32_t addr = arow * PITCH + ks * 32 + (sub >> 1) * 16;
                ldm_x4(ah[mi][0], ah[mi][1], ah[mi][2], ah[mi][3], Ah + addr);
                ldm_x4(al[mi][0], al[mi][1], al[mi][2], al[mi][3], Al + addr);
            }
#pragma unroll
            for (int p = 0; p < 2; ++p) {
                const int nrow = wn * 32 + p * 16 + r8 + (sub >> 1) * 8;
                const uint32_t addr = nrow * PITCH + ks * 32 + (sub & 1) * 16;
                uint32_t r0, r1, r2, r3;
                ldm_x4(r0, r1, r2, r3, Bh + addr);
                bh[2 * p][0] = r0; bh[2 * p][1] = r1;
                bh[2 * p + 1][0] = r2; bh[2 * p + 1][1] = r3;
                ldm_x4(r0, r1, r2, r3, Bl + addr);
                bl[2 * p][0] = r0; bl[2 * p][1] = r1;
                bl[2 * p + 1][0] = r2; bl[2 * p + 1][1] = r3;
            }
#pragma unroll
            for (int mi = 0; mi < 2; ++mi)
#pragma unroll
                for (int nj = 0; nj < 4; ++nj) {
                    mma16816(acc[mi][nj], ah[mi], bh[nj]);
                    mma16816(acc[mi][nj], ah[mi], bl[nj]);
                    mma16816(acc[mi][nj], al[mi], bh[nj]);
                }
        }
    };

    // ---- prologue ----
    {
        uint4 r[4];
        ldg_chunk(0, r);
        sts_chunk(0, r);
    }
    // ---- main loop ----
    for (int kc = 0; kc < nc; ++kc) {
        const int cur = kc & 1;
        __syncthreads();
        uint4 r[4];
        const bool more = (kc + 1 < nc);
        if (more) ldg_chunk(kc + 1, r);
        compute_stage(cur);
        if (more) sts_chunk(cur ^ 1, r);
    }

    // ---- epilogue ----
    const int g = lane >> 2;
    const int tq = lane & 3;
#pragma unroll
    for (int nj = 0; nj < 4; ++nj) {
        const int col = wn * 32 + nj * 8 + 2 * tq;
        const float2 bb = *(const float2*)(bias + col);
#pragma unroll
        for (int mi = 0; mi < 2; ++mi) {
            const int row0 = block_row + wm * 32 + mi * 16 + g;
            const int row1 = row0 + 8;
            float d0 = fmaxf(acc[mi][nj][0] + bb.x, 0.f);
            float d1 = fmaxf(acc[mi][nj][1] + bb.y, 0.f);
            float d2 = fmaxf(acc[mi][nj][2] + bb.x, 0.f);
            float d3 = fmaxf(acc[mi][nj][3] + bb.y, 0.f);
            if (row0 < N_NODES) {
                if (outf) *(float2*)(outf + (size_t)row0 * 128 + col) = make_float2(d0, d1);
                if (outh) *(__half2*)(outh + (size_t)row0 * 128 + col) =
                              __float22half2_rn(make_float2(d0, d1));
                if (outhi) {
                    uint32_t h, l; split2(d0, d1, h, l);
                    *(uint32_t*)(outhi + (size_t)row0 * 128 + col) = h;
                    *(uint32_t*)(outlo + (size_t)row0 * 128 + col) = l;
                }
            }
            if (row1 < N_NODES) {
                if (outf) *(float2*)(outf + (size_t)row1 * 128 + col) = make_float2(d2, d3);
                if (outh) *(__half2*)(outh + (size_t)row1 * 128 + col) =
                              __float22half2_rn(make_float2(d2, d3));
                if (outhi) {
                    uint32_t h, l; split2(d2, d3, h, l);
                    *(uint32_t*)(outhi + (size_t)row1 * 128 + col) = h;
                    *(uint32_t*)(outlo + (size_t)row1 * 128 + col) = l;
                }
            }
        }
    }
}

// ---------------- head: logits = t @ Wc1 + bc1  (N=32) ---------------------
__global__ void __launch_bounds__(256) head2_kernel(
    const float* __restrict__ t, const float* __restrict__ Wc1,
    const float* __restrict__ bc1, float* __restrict__ out)
{
    __shared__ float Ws[HIDC * N_TRUCK];
    __shared__ float bs[N_TRUCK];
    int tid = threadIdx.x;
#pragma unroll
    for (int r = 0; r < 4; ++r) {
        int idx = tid + r * 256;
        *(float4*)&Ws[idx * 4] = __ldg((const float4*)(Wc1 + idx * 4));
    }
    if (tid < N_TRUCK) bs[tid] = bc1[tid];
    __syncthreads();

    int row = blockIdx.x * 8 + (tid >> 5);
    int col = tid & 31;
    if (row >= N_NODES) return;
    const float* trow = t + (size_t)row * HIDC;
    float acc = bs[col];
#pragma unroll
    for (int k4 = 0; k4 < 32; ++k4) {
        float4 v = __ldg((const float4*)(trow + k4 * 4));
        acc += v.x * Ws[(k4 * 4 + 0) * N_TRUCK + col];
        acc += v.y * Ws[(k4 * 4 + 1) * N_TRUCK + col];
        acc += v.z * Ws[(k4 * 4 + 2) * N_TRUCK + col];
        acc += v.w * Ws[(k4 * 4 + 3) * N_TRUCK + col];
    }
    out[(size_t)row * N_TRUCK + col] = acc;
}

// ---------------- launch ----------------------------------------------------
extern "C" void kernel_launch(void* const* d_in, const int* in_sizes, int n_in,
                              void* d_out, int out_size)
{
    const float* x      = (const float*)d_in[0];
    const int*   ei     = (const int*)d_in[1];
    const float* W_rel0 = (const float*)d_in[2];
    const float* b_rel0 = (const float*)d_in[3];
    const float* W_root0= (const float*)d_in[4];
    const float* W_rel1 = (const float*)d_in[5];
    const float* b_rel1 = (const float*)d_in[6];
    const float* W_root1= (const float*)d_in[7];
    const float* W_rel2 = (const float*)d_in[8];
    const float* b_rel2 = (const float*)d_in[9];
    const float* W_root2= (const float*)d_in[10];
    const float* Wc0    = (const float*)d_in[11];
    const float* bc0    = (const float*)d_in[12];
    const float* Wc1    = (const float*)d_in[13];
    const float* bc1    = (const float*)d_in[14];
    float* out = (float*)d_out;

    const int* srcp = ei;
    const int* dstp = ei + N_EDGES;

    float *F; __half *hx, *hA, *hB;
    __nv_bfloat16 *p0h, *p0l, *p1h, *p1l, *agh, *agl, *wtb;
    cudaGetSymbolAddress((void**)&F,   g_F);
    cudaGetSymbolAddress((void**)&hx,  g_hx);
    cudaGetSymbolAddress((void**)&hA,  g_hA);
    cudaGetSymbolAddress((void**)&hB,  g_hB);
    cudaGetSymbolAddress((void**)&p0h, g_p0h);
    cudaGetSymbolAddress((void**)&p0l, g_p0l);
    cudaGetSymbolAddress((void**)&p1h, g_p1h);
    cudaGetSymbolAddress((void**)&p1l, g_p1l);
    cudaGetSymbolAddress((void**)&agh, g_agh);
    cudaGetSymbolAddress((void**)&agl, g_agl);
    cudaGetSymbolAddress((void**)&wtb, g_wtb);

    cudaFuncSetAttribute(gemm_mma, cudaFuncAttributeMaxDynamicSharedMemorySize, GEMM_SMEM);

    const int nbScan = (N_NODES + 1023) / 1024;

    // CSR build (dst-sorted)
    zero_cnt_kernel<<<(N_NODES + 255) / 256, 256>>>();
    hist_kernel<<<(N_EDGES + 255) / 256, 256>>>(dstp);
    scan_phase1<<<nbScan, 1024>>>();
    scan_phase2<<<1, 128>>>(nbScan);
    scan_phase3<<<(N_NODES + 255) / 256, 256>>>();
    fill_kernel<<<(N_EDGES + 255) / 256, 256>>>(srcp, dstp);

    // prep: split x (pairs + fp16), transpose+split weights
    const int n4 = N_NODES * HIDC / 4;
    split_kernel<<<(n4 + 255) / 256, 256>>>(x, p0h, p0l, hx, n4);
    wprep_kernel<<<(7 * 16384 + 255) / 256, 256>>>(W_rel0, W_root0, W_rel1, W_root1,
                                                   W_rel2, W_root2, Wc0);

    const int aggGrid  = (N_NODES * 32 + 255) / 256;
    const int gemmGrid = (N_NODES + 127) / 128;
    __nv_bfloat16* wt = wtb;   // slot i at wt + i*16384

    // layer 0: agg(fp16 x) ; gemm -> hA (fp16) + p1 pair
    agg_kernel<<<aggGrid, 256>>>(hx, agh, agl);
    gemm_mma<<<gemmGrid, 512, GEMM_SMEM>>>(agh, agl, p0h, p0l,
        wt + 0*16384, wt + 1*16384, wt + 2*16384, wt + 3*16384,
        b_rel0, nullptr, hA, p1h, p1l, 8, 4);
    // layer 1: agg(hA) ; gemm -> hB (fp16) + p0 pair
    agg_kernel<<<aggGrid, 256>>>(hA, agh, agl);
    gemm_mma<<<gemmGrid, 512, GEMM_SMEM>>>(agh, agl, p1h, p1l,
        wt + 4*16384, wt + 5*16384, wt + 6*16384, wt + 7*16384,
        b_rel1, nullptr, hB, p0h, p0l, 8, 4);
    // layer 2: agg(hB) ; gemm -> p1 pair only
    agg_kernel<<<aggGrid, 256>>>(hB, agh, agl);
    gemm_mma<<<gemmGrid, 512, GEMM_SMEM>>>(agh, agl, p0h, p0l,
        wt + 8*16384, wt + 9*16384, wt + 10*16384, wt + 11*16384,
        b_rel2, nullptr, nullptr, p1h, p1l, 8, 4);
    // head linear 1: p1 pair -> F (fp32), K=128
    gemm_mma<<<gemmGrid, 512, GEMM_SMEM>>>(nullptr, nullptr, p1h, p1l,
        nullptr, nullptr, wt + 12*16384, wt + 13*16384,
        bc0, F, nullptr, nullptr, nullptr, 4, 0);
    // head linear 2
    head2_kernel<<<(N_NODES + 7) / 8, 256>>>(F, Wc1, bc1, out);
    (void)in_sizes; (void)n_in; (void)out_size;
}

// round 14
// speedup vs baseline: 1.0875x; 1.0875x over previous
#include <cuda_runtime.h>
#include <cuda_bf16.h>
#include <cuda_fp16.h>
#include <cstdint>
#include <cstddef>

#define N_NODES 100000
#define N_EDGES 1600000
#define HIDC    128
#define N_TRUCK 32

// ---------------- device scratch ------------------------------------------
__device__ __half        g_hx  [(size_t)N_NODES * HIDC];
__device__ __half        g_hA  [(size_t)N_NODES * HIDC];
__device__ __half        g_hB  [(size_t)N_NODES * HIDC];
__device__ __nv_bfloat16 g_p0h [(size_t)N_NODES * HIDC];
__device__ __nv_bfloat16 g_p0l [(size_t)N_NODES * HIDC];
__device__ __nv_bfloat16 g_p1h [(size_t)N_NODES * HIDC];
__device__ __nv_bfloat16 g_p1l [(size_t)N_NODES * HIDC];
__device__ __nv_bfloat16 g_agh [(size_t)N_NODES * HIDC];
__device__ __nv_bfloat16 g_agl [(size_t)N_NODES * HIDC];
__device__ __nv_bfloat16 g_wtb [14 * 16384];
__device__ int   g_cnt[N_NODES];
__device__ int   g_cursor[N_NODES];
__device__ int   g_rowptr[N_NODES + 1];
__device__ int   g_srcsorted[N_EDGES];
__device__ int   g_blocksums[128];

// ---------------- helpers ---------------------------------------------------
__device__ __forceinline__ uint32_t smem_u32(const void* p) {
    uint32_t a;
    asm("{ .reg .u64 t; cvta.to.shared.u64 t, %1; cvt.u32.u64 %0, t; }" : "=r"(a) : "l"(p));
    return a;
}
__device__ __forceinline__ void split2(float a, float b, uint32_t& h, uint32_t& l) {
    __nv_bfloat162 hh = __floats2bfloat162_rn(a, b);
    __nv_bfloat162 ll = __floats2bfloat162_rn(a - __bfloat162float(hh.x),
                                              b - __bfloat162float(hh.y));
    h = *reinterpret_cast<uint32_t*>(&hh);
    l = *reinterpret_cast<uint32_t*>(&ll);
}
__device__ __forceinline__ void split4(float a, float b, float c, float d,
                                       uint32_t& h01, uint32_t& h23,
                                       uint32_t& l01, uint32_t& l23) {
    split2(a, b, h01, l01);
    split2(c, d, h23, l23);
}
__device__ __forceinline__ void ldm_x4(uint32_t& r0, uint32_t& r1, uint32_t& r2,
                                       uint32_t& r3, uint32_t addr) {
    asm volatile("ldmatrix.sync.aligned.m8n8.x4.shared.b16 {%0,%1,%2,%3}, [%4];"
                 : "=r"(r0), "=r"(r1), "=r"(r2), "=r"(r3) : "r"(addr));
}
__device__ __forceinline__ void mma16816(float* c, const uint32_t* a, const uint32_t* b) {
    asm volatile("mma.sync.aligned.m16n8k16.row.col.f32.bf16.bf16.f32 "
                 "{%0,%1,%2,%3}, {%4,%5,%6,%7}, {%8,%9}, {%0,%1,%2,%3};"
                 : "+f"(c[0]), "+f"(c[1]), "+f"(c[2]), "+f"(c[3])
                 : "r"(a[0]), "r"(a[1]), "r"(a[2]), "r"(a[3]), "r"(b[0]), "r"(b[1]));
}

// ---------------- CSR build ------------------------------------------------
__global__ void zero_cnt_kernel() {
    int i = blockIdx.x * blockDim.x + threadIdx.x;
    if (i < N_NODES) g_cnt[i] = 0;
}
__global__ void hist_kernel(const int* __restrict__ dst) {
    int i = blockIdx.x * blockDim.x + threadIdx.x;
    if (i < N_EDGES) atomicAdd(&g_cnt[dst[i]], 1);
}
__global__ void scan_phase1() {
    __shared__ int sh[1024];
    int i = blockIdx.x * 1024 + threadIdx.x;
    int v = (i < N_NODES) ? g_cnt[i] : 0;
    sh[threadIdx.x] = v;
    __syncthreads();
    for (int off = 1; off < 1024; off <<= 1) {
        int t = (threadIdx.x >= off) ? sh[threadIdx.x - off] : 0;
        __syncthreads();
        sh[threadIdx.x] += t;
        __syncthreads();
    }
    if (i < N_NODES) g_rowptr[i] = sh[threadIdx.x];
    if (threadIdx.x == 1023) g_blocksums[blockIdx.x] = sh[1023];
}
__global__ void scan_phase2(int nb) {
    __shared__ int sh[128];
    int t = threadIdx.x;
    int v = (t < nb) ? g_blocksums[t] : 0;
    sh[t] = v;
    __syncthreads();
    for (int off = 1; off < 128; off <<= 1) {
        int u = (t >= off) ? sh[t - off] : 0;
        __syncthreads();
        sh[t] += u;
        __syncthreads();
    }
    if (t < nb) g_blocksums[t] = sh[t] - v;   // exclusive
}
__global__ void scan_phase3() {
    int i = blockIdx.x * blockDim.x + threadIdx.x;
    if (i < N_NODES) {
        int excl = g_rowptr[i] - g_cnt[i] + g_blocksums[i >> 10];
        g_rowptr[i] = excl;
        g_cursor[i] = excl;
    }
    if (i == 0) g_rowptr[N_NODES] = N_EDGES;
}
__global__ void fill_kernel(const int* __restrict__ src, const int* __restrict__ dst) {
    int i = blockIdx.x * blockDim.x + threadIdx.x;
    if (i < N_EDGES) {
        int p = atomicAdd(&g_cursor[dst[i]], 1);
        g_srcsorted[p] = src[i];
    }
}

// ---------------- split x -> bf16 hi/lo pairs + fp16 copy -------------------
__global__ void split_kernel(const float* __restrict__ src,
                             __nv_bfloat16* __restrict__ hi,
                             __nv_bfloat16* __restrict__ lo,
                             __half* __restrict__ h16, int n4) {
    int i = blockIdx.x * blockDim.x + threadIdx.x;
    if (i >= n4) return;
    float4 v = __ldg((const float4*)src + i);
    uint32_t h01, h23, l01, l23;
    split4(v.x, v.y, v.z, v.w, h01, h23, l01, l23);
    *(uint2*)(hi + (size_t)i * 4) = make_uint2(h01, h23);
    *(uint2*)(lo + (size_t)i * 4) = make_uint2(l01, l23);
    __half2 p0 = __float22half2_rn(make_float2(v.x, v.y));
    __half2 p1 = __float22half2_rn(make_float2(v.z, v.w));
    *(uint2*)(h16 + (size_t)i * 4) =
        make_uint2(*reinterpret_cast<uint32_t*>(&p0), *reinterpret_cast<uint32_t*>(&p1));
}

// ---------------- weight prep: transpose + split ----------------------------
__global__ void wprep_kernel(const float* __restrict__ w0, const float* __restrict__ w1,
                             const float* __restrict__ w2, const float* __restrict__ w3,
                             const float* __restrict__ w4, const float* __restrict__ w5,
                             const float* __restrict__ w6) {
    int gid = blockIdx.x * blockDim.x + threadIdx.x;
    if (gid >= 7 * 16384) return;
    int m = gid >> 14;
    int r = gid & 16383;
    int n = r >> 7;
    int k = r & 127;
    const float* W = (m == 0) ? w0 : (m == 1) ? w1 : (m == 2) ? w2 : (m == 3) ? w3
                   : (m == 4) ? w4 : (m == 5) ? w5 : w6;
    float v = __ldg(W + k * 128 + n);
    __nv_bfloat16 h = __float2bfloat16(v);
    __nv_bfloat16 l = __float2bfloat16(v - __bfloat162float(h));
    int hidx = (m < 6) ? ((m >> 1) * 4 + (m & 1) * 2) : 12;
    g_wtb[(size_t)hidx * 16384 + n * 128 + k] = h;
    g_wtb[(size_t)(hidx + 1) * 16384 + n * 128 + k] = l;
}

// ---------------- aggregation: warp per node, fp16 gather, x2 unroll -------
__global__ void __launch_bounds__(256) agg_kernel(const __half* __restrict__ h,
                                                  __nv_bfloat16* __restrict__ ahi,
                                                  __nv_bfloat16* __restrict__ alo) {
    int gw   = (blockIdx.x * blockDim.x + threadIdx.x) >> 5;
    int lane = threadIdx.x & 31;
    if (gw >= N_NODES) return;
    int beg = g_rowptr[gw];
    int end = g_rowptr[gw + 1];
    float x0 = 0.f, x1 = 0.f, x2 = 0.f, x3 = 0.f;
    float y0 = 0.f, y1 = 0.f, y2 = 0.f, y3 = 0.f;
    int e = beg;
    for (; e + 2 <= end; e += 2) {
        int s0 = __ldg(g_srcsorted + e);
        int s1 = __ldg(g_srcsorted + e + 1);
        uint2 u0 = __ldg((const uint2*)(h + (size_t)s0 * HIDC + lane * 4));
        uint2 u1 = __ldg((const uint2*)(h + (size_t)s1 * HIDC + lane * 4));
        float2 f;
        f = __half22float2(*reinterpret_cast<__half2*>(&u0.x)); x0 += f.x; x1 += f.y;
        f = __half22float2(*reinterpret_cast<__half2*>(&u0.y)); x2 += f.x; x3 += f.y;
        f = __half22float2(*reinterpret_cast<__half2*>(&u1.x)); y0 += f.x; y1 += f.y;
        f = __half22float2(*reinterpret_cast<__half2*>(&u1.y)); y2 += f.x; y3 += f.y;
    }
    if (e < end) {
        int s0 = __ldg(g_srcsorted + e);
        uint2 u0 = __ldg((const uint2*)(h + (size_t)s0 * HIDC + lane * 4));
        float2 f;
        f = __half22float2(*reinterpret_cast<__half2*>(&u0.x)); x0 += f.x; x1 += f.y;
        f = __half22float2(*reinterpret_cast<__half2*>(&u0.y)); x2 += f.x; x3 += f.y;
    }
    x0 += y0; x1 += y1; x2 += y2; x3 += y3;
    uint32_t h01, h23, l01, l23;
    split4(x0, x1, x2, x3, h01, h23, l01, l23);
    size_t off = (size_t)gw * HIDC + lane * 4;
    *(uint2*)(ahi + off) = make_uint2(h01, h23);
    *(uint2*)(alo + off) = make_uint2(l01, l23);
}

// ---------------- mma.sync bf16x3 GEMM (R10 config: 256thr, KC=64, 2-stage) -
// out = act( [A1|A2] @ [B1;B2] + bias ); optional fused head2:
// if logits != null, h = relu(...) is staged in smem and logits = h@Wc1+bc1.
#define KC       64
#define PITCH    144                       // (64+8) halves * 2B, conflict-free ldmatrix
#define TILE_B   (128 * PITCH)             // 18432 B
#define STAGE_B  (4 * TILE_B)              // Ahi, Alo, Bhi, Blo = 73728 B
#define GEMM_SMEM (2 * STAGE_B)            // 147456 B
#define HPITCH   132                       // fp32 h row pitch (floats) for fused head

__global__ void __launch_bounds__(256, 1) gemm_mma(
    const __nv_bfloat16* __restrict__ a1h, const __nv_bfloat16* __restrict__ a1l,
    const __nv_bfloat16* __restrict__ a2h, const __nv_bfloat16* __restrict__ a2l,
    const __nv_bfloat16* __restrict__ b1h, const __nv_bfloat16* __restrict__ b1l,
    const __nv_bfloat16* __restrict__ b2h, const __nv_bfloat16* __restrict__ b2l,
    const float* __restrict__ bias,
    __half* __restrict__ outh,
    __nv_bfloat16* __restrict__ outhi, __nv_bfloat16* __restrict__ outlo,
    const float* __restrict__ Wc1, const float* __restrict__ bc1,
    float* __restrict__ logits,
    int nc, int k1c)
{
    extern __shared__ char smem[];
    const uint32_t sbase = smem_u32(smem);
    const int tid  = threadIdx.x;
    const int wid  = tid >> 5;
    const int lane = tid & 31;
    const int wm = wid >> 2;            // 0..1  (64-row slab)
    const int wn = wid & 3;             // 0..3  (32-col slab)
    const int block_row = blockIdx.x * 128;

    float acc[4][4][4];
#pragma unroll
    for (int i = 0; i < 4; ++i)
#pragma unroll
        for (int j = 0; j < 4; ++j)
#pragma unroll
            for (int k = 0; k < 4; ++k) acc[i][j][k] = 0.f;

    auto pick = [&](int kc, const __nv_bfloat16*& ah, const __nv_bfloat16*& al,
                    const __nv_bfloat16*& bh, const __nv_bfloat16*& bl, int& acol) {
        if (kc < k1c) { ah = a1h; al = a1l; bh = b1h; bl = b1l; acol = kc * KC; }
        else          { ah = a2h; al = a2l; bh = b2h; bl = b2l; acol = (kc - k1c) * KC; }
    };

    auto ldg_batch = [&](int kc, int tbeg, uint4* regs) {
        const __nv_bfloat16 *ah, *al, *bh, *bl; int acol;
        pick(kc, ah, al, bh, bl, acol);
#pragma unroll
        for (int t = 0; t < 8; ++t) {
            const int slot = tbeg + t;
            const int buf = slot >> 2;
            const int w = tid + (slot & 3) * 256;
            const int row = w >> 3;
            const int q = w & 7;
            uint4 v = make_uint4(0, 0, 0, 0);
            if (buf < 2) {
                int grow = block_row + row;
                if (grow < N_NODES) {
                    const __nv_bfloat16* src = (buf == 0) ? ah : al;
                    v = *(const uint4*)(src + (size_t)grow * 128 + acol + q * 8);
                }
            } else {
                const __nv_bfloat16* src = (buf == 2) ? bh : bl;
                v = *(const uint4*)(src + (size_t)row * 128 + acol + q * 8);
            }
            regs[t] = v;
        }
    };
    auto sts_batch = [&](int stage, int tbeg, const uint4* regs) {
#pragma unroll
        for (int t = 0; t < 8; ++t) {
            const int slot = tbeg + t;
            const int buf = slot >> 2;
            const int w = tid + (slot & 3) * 256;
            const int row = w >> 3;
            const int q = w & 7;
            *(uint4*)(smem + stage * STAGE_B + buf * TILE_B + row * PITCH + q * 16) = regs[t];
        }
    };

    const int r8  = lane & 7;
    const int sub = lane >> 3;
    auto compute2 = [&](int stage, int ks0) {
        const uint32_t so = sbase + stage * STAGE_B;
        const uint32_t Ah = so;
        const uint32_t Al = so + TILE_B;
        const uint32_t Bh = so + 2 * TILE_B;
        const uint32_t Bl = so + 3 * TILE_B;
#pragma unroll
        for (int ks = ks0; ks < ks0 + 2; ++ks) {
            uint32_t ah[4][4], al[4][4], bh[4][2], bl[4][2];
#pragma unroll
            for (int mi = 0; mi < 4; ++mi) {
                const int arow = wm * 64 + mi * 16 + r8 + (sub & 1) * 8;
                const uint32_t addr = arow * PITCH + ks * 32 + (sub >> 1) * 16;
                ldm_x4(ah[mi][0], ah[mi][1], ah[mi][2], ah[mi][3], Ah + addr);
                ldm_x4(al[mi][0], al[mi][1], al[mi][2], al[mi][3], Al + addr);
            }
#pragma unroll
            for (int p = 0; p < 2; ++p) {
                const int nrow = wn * 32 + p * 16 + r8 + (sub >> 1) * 8;
                const uint32_t addr = nrow * PITCH + ks * 32 + (sub & 1) * 16;
                uint32_t r0, r1, r2, r3;
                ldm_x4(r0, r1, r2, r3, Bh + addr);
                bh[2 * p][0] = r0; bh[2 * p][1] = r1;
                bh[2 * p + 1][0] = r2; bh[2 * p + 1][1] = r3;
                ldm_x4(r0, r1, r2, r3, Bl + addr);
                bl[2 * p][0] = r0; bl[2 * p][1] = r1;
                bl[2 * p + 1][0] = r2; bl[2 * p + 1][1] = r3;
            }
#pragma unroll
            for (int mi = 0; mi < 4; ++mi)
#pragma unroll
                for (int nj = 0; nj < 4; ++nj) {
                    mma16816(acc[mi][nj], ah[mi], bh[nj]);
                    mma16816(acc[mi][nj], ah[mi], bl[nj]);
                    mma16816(acc[mi][nj], al[mi], bh[nj]);
                }
        }
    };

    // ---- prologue: chunk 0 into stage 0 ----
    {
        uint4 r[8];
        ldg_batch(0, 0, r); sts_batch(0, 0, r);
        ldg_batch(0, 8, r); sts_batch(0, 8, r);
    }

    // ---- main loop ----
    for (int kc = 0; kc < nc; ++kc) {
        const int cur = kc & 1;
        const int nxt = cur ^ 1;
        __syncthreads();
        uint4 r[8];
        const bool more = (kc + 1 < nc);
        if (more) ldg_batch(kc + 1, 0, r);
        compute2(cur, 0);
        if (more) { sts_batch(nxt, 0, r); ldg_batch(kc + 1, 8, r); }
        compute2(cur, 2);
        if (more) sts_batch(nxt, 8, r);
    }

    // ---- epilogue ----
    const int g = lane >> 2;
    const int tq = lane & 3;
    float* hs = (float*)smem;                 // fused-head staging (reuses stages)
    if (logits) __syncthreads();              // stage reads done before overwrite
#pragma unroll
    for (int nj = 0; nj < 4; ++nj) {
        const int col = wn * 32 + nj * 8 + 2 * tq;
        const float2 bb = *(const float2*)(bias + col);
#pragma unroll
        for (int mi = 0; mi < 4; ++mi) {
            const int row0 = block_row + wm * 64 + mi * 16 + g;
            const int row1 = row0 + 8;
            const int lr0 = wm * 64 + mi * 16 + g;
            const int lr1 = lr0 + 8;
            float d0 = fmaxf(acc[mi][nj][0] + bb.x, 0.f);
            float d1 = fmaxf(acc[mi][nj][1] + bb.y, 0.f);
            float d2 = fmaxf(acc[mi][nj][2] + bb.x, 0.f);
            float d3 = fmaxf(acc[mi][nj][3] + bb.y, 0.f);
            if (logits) {
                hs[lr0 * HPITCH + col]     = d0;
                hs[lr0 * HPITCH + col + 1] = d1;
                hs[lr1 * HPITCH + col]     = d2;
                hs[lr1 * HPITCH + col + 1] = d3;
            } else {
                if (row0 < N_NODES) {
                    if (outh) *(__half2*)(outh + (size_t)row0 * 128 + col) =
                                  __float22half2_rn(make_float2(d0, d1));
                    uint32_t h, l; split2(d0, d1, h, l);
                    *(uint32_t*)(outhi + (size_t)row0 * 128 + col) = h;
                    *(uint32_t*)(outlo + (size_t)row0 * 128 + col) = l;
                }
                if (row1 < N_NODES) {
                    if (outh) *(__half2*)(outh + (size_t)row1 * 128 + col) =
                                  __float22half2_rn(make_float2(d2, d3));
                    uint32_t h, l; split2(d2, d3, h, l);
                    *(uint32_t*)(outhi + (size_t)row1 * 128 + col) = h;
                    *(uint32_t*)(outlo + (size_t)row1 * 128 + col) = l;
                }
            }
        }
    }

    // ---- fused head2: logits = h @ Wc1 + bc1 (N_TRUCK=32) ----
    if (logits) {
        __syncthreads();
        const float bcv = __ldg(bc1 + lane);
#pragma unroll 1
        for (int rr = 0; rr < 16; ++rr) {
            const int lrow = wid * 16 + rr;
            const int grow = block_row + lrow;
            if (grow >= N_NODES) break;
            const float* hrow = hs + lrow * HPITCH;
            float a0 = bcv, a1 = 0.f, a2 = 0.f, a3 = 0.f;
#pragma unroll 8
            for (int k = 0; k < 128; k += 4) {
                a0 += hrow[k + 0] * __ldg(Wc1 + (k + 0) * N_TRUCK + lane);
                a1 += hrow[k + 1] * __ldg(Wc1 + (k + 1) * N_TRUCK + lane);
                a2 += hrow[k + 2] * __ldg(Wc1 + (k + 2) * N_TRUCK + lane);
                a3 += hrow[k + 3] * __ldg(Wc1 + (k + 3) * N_TRUCK + lane);
            }
            logits[(size_t)grow * N_TRUCK + lane] = a0 + a1 + a2 + a3;
        }
    }
}

// ---------------- launch ----------------------------------------------------
extern "C" void kernel_launch(void* const* d_in, const int* in_sizes, int n_in,
                              void* d_out, int out_size)
{
    const float* x      = (const float*)d_in[0];
    const int*   ei     = (const int*)d_in[1];
    const float* W_rel0 = (const float*)d_in[2];
    const float* b_rel0 = (const float*)d_in[3];
    const float* W_root0= (const float*)d_in[4];
    const float* W_rel1 = (const float*)d_in[5];
    const float* b_rel1 = (const float*)d_in[6];
    const float* W_root1= (const float*)d_in[7];
    const float* W_rel2 = (const float*)d_in[8];
    const float* b_rel2 = (const float*)d_in[9];
    const float* W_root2= (const float*)d_in[10];
    const float* Wc0    = (const float*)d_in[11];
    const float* bc0    = (const float*)d_in[12];
    const float* Wc1    = (const float*)d_in[13];
    const float* bc1    = (const float*)d_in[14];
    float* out = (float*)d_out;

    const int* srcp = ei;
    const int* dstp = ei + N_EDGES;

    __half *hx, *hA, *hB;
    __nv_bfloat16 *p0h, *p0l, *p1h, *p1l, *agh, *agl, *wtb;
    cudaGetSymbolAddress((void**)&hx,  g_hx);
    cudaGetSymbolAddress((void**)&hA,  g_hA);
    cudaGetSymbolAddress((void**)&hB,  g_hB);
    cudaGetSymbolAddress((void**)&p0h, g_p0h);
    cudaGetSymbolAddress((void**)&p0l, g_p0l);
    cudaGetSymbolAddress((void**)&p1h, g_p1h);
    cudaGetSymbolAddress((void**)&p1l, g_p1l);
    cudaGetSymbolAddress((void**)&agh, g_agh);
    cudaGetSymbolAddress((void**)&agl, g_agl);
    cudaGetSymbolAddress((void**)&wtb, g_wtb);

    cudaFuncSetAttribute(gemm_mma, cudaFuncAttributeMaxDynamicSharedMemorySize, GEMM_SMEM);

    const int nbScan = (N_NODES + 1023) / 1024;

    // CSR build (dst-sorted)
    zero_cnt_kernel<<<(N_NODES + 255) / 256, 256>>>();
    hist_kernel<<<(N_EDGES + 255) / 256, 256>>>(dstp);
    scan_phase1<<<nbScan, 1024>>>();
    scan_phase2<<<1, 128>>>(nbScan);
    scan_phase3<<<(N_NODES + 255) / 256, 256>>>();
    fill_kernel<<<(N_EDGES + 255) / 256, 256>>>(srcp, dstp);

    // prep: split x (pairs + fp16), transpose+split weights
    const int n4 = N_NODES * HIDC / 4;
    split_kernel<<<(n4 + 255) / 256, 256>>>(x, p0h, p0l, hx, n4);
    wprep_kernel<<<(7 * 16384 + 255) / 256, 256>>>(W_rel0, W_root0, W_rel1, W_root1,
                                                   W_rel2, W_root2, Wc0);

    const int aggGrid  = (N_NODES * 32 + 255) / 256;
    const int gemmGrid = (N_NODES + 127) / 128;
    __nv_bfloat16* wt = wtb;   // slot i at wt + i*16384

    // layer 0: agg(fp16 x) ; gemm -> hA (fp16) + p1 pair
    agg_kernel<<<aggGrid, 256>>>(hx, agh, agl);
    gemm_mma<<<gemmGrid, 256, GEMM_SMEM>>>(agh, agl, p0h, p0l,
        wt + 0*16384, wt + 1*16384, wt + 2*16384, wt + 3*16384,
        b_rel0, hA, p1h, p1l, nullptr, nullptr, nullptr, 4, 2);
    // layer 1: agg(hA) ; gemm -> hB (fp16) + p0 pair
    agg_kernel<<<aggGrid, 256>>>(hA, agh, agl);
    gemm_mma<<<gemmGrid, 256, GEMM_SMEM>>>(agh, agl, p1h, p1l,
        wt + 4*16384, wt + 5*16384, wt + 6*16384, wt + 7*16384,
        b_rel1, hB, p0h, p0l, nullptr, nullptr, nullptr, 4, 2);
    // layer 2: agg(hB) ; gemm -> p1 pair only
    agg_kernel<<<aggGrid, 256>>>(hB, agh, agl);
    gemm_mma<<<gemmGrid, 256, GEMM_SMEM>>>(agh, agl, p0h, p0l,
        wt + 8*16384, wt + 9*16384, wt + 10*16384, wt + 11*16384,
        b_rel2, nullptr, p1h, p1l, nullptr, nullptr, nullptr, 4, 2);
    // head: p1 pair @ Wc0 + bc0 -> relu -> @ Wc1 + bc1 -> logits (fused)
    gemm_mma<<<gemmGrid, 256, GEMM_SMEM>>>(nullptr, nullptr, p1h, p1l,
        nullptr, nullptr, wt + 12*16384, wt + 13*16384,
        bc0, nullptr, nullptr, nullptr, Wc1, bc1, out, 2, 0);
    (void)in_sizes; (void)n_in; (void)out_size;
}

// round 15
// speedup vs baseline: 1.2764x; 1.1737x over previous
#include <cuda_runtime.h>
#include <cuda_bf16.h>
#include <cuda_fp16.h>
#include <cstdint>
#include <cstddef>

#define N_NODES 100000
#define N_EDGES 1600000
#define HIDC    128
#define N_TRUCK 32

// ---------------- device scratch ------------------------------------------
__device__ __half        g_hx [(size_t)N_NODES * HIDC];   // fp16 x
__device__ __half        g_hA [(size_t)N_NODES * HIDC];   // fp16 h1
__device__ __half        g_hB [(size_t)N_NODES * HIDC];   // fp16 h2
__device__ __half        g_hC [(size_t)N_NODES * HIDC];   // fp16 h3
__device__ __half        g_ag [(size_t)N_NODES * HIDC];   // fp16 agg result
__device__ __nv_bfloat16 g_wtb[14 * 16384];               // transposed split weights
__device__ int   g_cnt[N_NODES];
__device__ int   g_cursor[N_NODES];
__device__ int   g_rowptr[N_NODES + 1];
__device__ int   g_srcsorted[N_EDGES];
__device__ int   g_blocksums[128];

// ---------------- helpers ---------------------------------------------------
__device__ __forceinline__ uint32_t smem_u32(const void* p) {
    uint32_t a;
    asm("{ .reg .u64 t; cvta.to.shared.u64 t, %1; cvt.u32.u64 %0, t; }" : "=r"(a) : "l"(p));
    return a;
}
__device__ __forceinline__ void split2(float a, float b, uint32_t& h, uint32_t& l) {
    __nv_bfloat162 hh = __floats2bfloat162_rn(a, b);
    __nv_bfloat162 ll = __floats2bfloat162_rn(a - __bfloat162float(hh.x),
                                              b - __bfloat162float(hh.y));
    h = *reinterpret_cast<uint32_t*>(&hh);
    l = *reinterpret_cast<uint32_t*>(&ll);
}
__device__ __forceinline__ void ldm_x4(uint32_t& r0, uint32_t& r1, uint32_t& r2,
                                       uint32_t& r3, uint32_t addr) {
    asm volatile("ldmatrix.sync.aligned.m8n8.x4.shared.b16 {%0,%1,%2,%3}, [%4];"
                 : "=r"(r0), "=r"(r1), "=r"(r2), "=r"(r3) : "r"(addr));
}
__device__ __forceinline__ void mma16816(float* c, const uint32_t* a, const uint32_t* b) {
    asm volatile("mma.sync.aligned.m16n8k16.row.col.f32.bf16.bf16.f32 "
                 "{%0,%1,%2,%3}, {%4,%5,%6,%7}, {%8,%9}, {%0,%1,%2,%3};"
                 : "+f"(c[0]), "+f"(c[1]), "+f"(c[2]), "+f"(c[3])
                 : "r"(a[0]), "r"(a[1]), "r"(a[2]), "r"(a[3]), "r"(b[0]), "r"(b[1]));
}

// ---------------- CSR build ------------------------------------------------
__global__ void zero_cnt_kernel() {
    int i = blockIdx.x * blockDim.x + threadIdx.x;
    if (i < N_NODES) g_cnt[i] = 0;
}
__global__ void hist_kernel(const int* __restrict__ dst) {
    int i = blockIdx.x * blockDim.x + threadIdx.x;
    if (i < N_EDGES) atomicAdd(&g_cnt[dst[i]], 1);
}
__global__ void scan_phase1() {
    __shared__ int sh[1024];
    int i = blockIdx.x * 1024 + threadIdx.x;
    int v = (i < N_NODES) ? g_cnt[i] : 0;
    sh[threadIdx.x] = v;
    __syncthreads();
    for (int off = 1; off < 1024; off <<= 1) {
        int t = (threadIdx.x >= off) ? sh[threadIdx.x - off] : 0;
        __syncthreads();
        sh[threadIdx.x] += t;
        __syncthreads();
    }
    if (i < N_NODES) g_rowptr[i] = sh[threadIdx.x];
    if (threadIdx.x == 1023) g_blocksums[blockIdx.x] = sh[1023];
}
__global__ void scan_phase2(int nb) {
    __shared__ int sh[128];
    int t = threadIdx.x;
    int v = (t < nb) ? g_blocksums[t] : 0;
    sh[t] = v;
    __syncthreads();
    for (int off = 1; off < 128; off <<= 1) {
        int u = (t >= off) ? sh[t - off] : 0;
        __syncthreads();
        sh[t] += u;
        __syncthreads();
    }
    if (t < nb) g_blocksums[t] = sh[t] - v;   // exclusive
}
__global__ void scan_phase3() {
    int i = blockIdx.x * blockDim.x + threadIdx.x;
    if (i < N_NODES) {
        int excl = g_rowptr[i] - g_cnt[i] + g_blocksums[i >> 10];
        g_rowptr[i] = excl;
        g_cursor[i] = excl;
    }
    if (i == 0) g_rowptr[N_NODES] = N_EDGES;
}
__global__ void fill_kernel(const int* __restrict__ src, const int* __restrict__ dst) {
    int i = blockIdx.x * blockDim.x + threadIdx.x;
    if (i < N_EDGES) {
        int p = atomicAdd(&g_cursor[dst[i]], 1);
        g_srcsorted[p] = src[i];
    }
}

// ---------------- split x -> fp16 copy --------------------------------------
__global__ void split_kernel(const float* __restrict__ src,
                             __half* __restrict__ h16, int n4) {
    int i = blockIdx.x * blockDim.x + threadIdx.x;
    if (i >= n4) return;
    float4 v = __ldg((const float4*)src + i);
    __half2 p0 = __float22half2_rn(make_float2(v.x, v.y));
    __half2 p1 = __float22half2_rn(make_float2(v.z, v.w));
    *(uint2*)(h16 + (size_t)i * 4) =
        make_uint2(*reinterpret_cast<uint32_t*>(&p0), *reinterpret_cast<uint32_t*>(&p1));
}

// ---------------- weight prep: transpose + split ----------------------------
__global__ void wprep_kernel(const float* __restrict__ w0, const float* __restrict__ w1,
                             const float* __restrict__ w2, const float* __restrict__ w3,
                             const float* __restrict__ w4, const float* __restrict__ w5,
                             const float* __restrict__ w6) {
    int gid = blockIdx.x * blockDim.x + threadIdx.x;
    if (gid >= 7 * 16384) return;
    int m = gid >> 14;
    int r = gid & 16383;
    int n = r >> 7;
    int k = r & 127;
    const float* W = (m == 0) ? w0 : (m == 1) ? w1 : (m == 2) ? w2 : (m == 3) ? w3
                   : (m == 4) ? w4 : (m == 5) ? w5 : w6;
    float v = __ldg(W + k * 128 + n);
    __nv_bfloat16 h = __float2bfloat16(v);
    __nv_bfloat16 l = __float2bfloat16(v - __bfloat162float(h));
    int hidx = (m < 6) ? ((m >> 1) * 4 + (m & 1) * 2) : 12;
    g_wtb[(size_t)hidx * 16384 + n * 128 + k] = h;
    g_wtb[(size_t)(hidx + 1) * 16384 + n * 128 + k] = l;
}

// ---------------- aggregation: warp per node, fp16 in, fp16 out ------------
__global__ void __launch_bounds__(256) agg_kernel(const __half* __restrict__ h,
                                                  __half* __restrict__ aout) {
    int gw   = (blockIdx.x * blockDim.x + threadIdx.x) >> 5;
    int lane = threadIdx.x & 31;
    if (gw >= N_NODES) return;
    int beg = g_rowptr[gw];
    int end = g_rowptr[gw + 1];
    float x0 = 0.f, x1 = 0.f, x2 = 0.f, x3 = 0.f;
    float y0 = 0.f, y1 = 0.f, y2 = 0.f, y3 = 0.f;
    int e = beg;
    for (; e + 2 <= end; e += 2) {
        int s0 = __ldg(g_srcsorted + e);
        int s1 = __ldg(g_srcsorted + e + 1);
        uint2 u0 = __ldg((const uint2*)(h + (size_t)s0 * HIDC + lane * 4));
        uint2 u1 = __ldg((const uint2*)(h + (size_t)s1 * HIDC + lane * 4));
        float2 f;
        f = __half22float2(*reinterpret_cast<__half2*>(&u0.x)); x0 += f.x; x1 += f.y;
        f = __half22float2(*reinterpret_cast<__half2*>(&u0.y)); x2 += f.x; x3 += f.y;
        f = __half22float2(*reinterpret_cast<__half2*>(&u1.x)); y0 += f.x; y1 += f.y;
        f = __half22float2(*reinterpret_cast<__half2*>(&u1.y)); y2 += f.x; y3 += f.y;
    }
    if (e < end) {
        int s0 = __ldg(g_srcsorted + e);
        uint2 u0 = __ldg((const uint2*)(h + (size_t)s0 * HIDC + lane * 4));
        float2 f;
        f = __half22float2(*reinterpret_cast<__half2*>(&u0.x)); x0 += f.x; x1 += f.y;
        f = __half22float2(*reinterpret_cast<__half2*>(&u0.y)); x2 += f.x; x3 += f.y;
    }
    x0 += y0; x1 += y1; x2 += y2; x3 += y3;
    __half2 o0 = __float22half2_rn(make_float2(x0, x1));
    __half2 o1 = __float22half2_rn(make_float2(x2, x3));
    *(uint2*)(aout + (size_t)gw * HIDC + lane * 4) =
        make_uint2(*reinterpret_cast<uint32_t*>(&o0), *reinterpret_cast<uint32_t*>(&o1));
}

// ---------------- mma.sync bf16x3 GEMM, fp16 A with in-register split ------
// out = act( [A1|A2] @ [B1;B2] + bias ); A sources are fp16 (exact hi/lo split
// done in the load path). Optional fused head2 via logits != null.
#define KC       64
#define PITCH    144                       // (64+8) halves * 2B, conflict-free ldmatrix
#define TILE_B   (128 * PITCH)             // 18432 B
#define STAGE_B  (4 * TILE_B)              // Ahi, Alo, Bhi, Blo = 73728 B
#define GEMM_SMEM (2 * STAGE_B)            // 147456 B
#define HPITCH   132                       // fp32 h row pitch (floats) for fused head

__global__ void __launch_bounds__(256, 1) gemm_mma(
    const __half* __restrict__ a1f, const __half* __restrict__ a2f,
    const __nv_bfloat16* __restrict__ b1h, const __nv_bfloat16* __restrict__ b1l,
    const __nv_bfloat16* __restrict__ b2h, const __nv_bfloat16* __restrict__ b2l,
    const float* __restrict__ bias,
    __half* __restrict__ outh,
    const float* __restrict__ Wc1, const float* __restrict__ bc1,
    float* __restrict__ logits,
    int nc, int k1c)
{
    extern __shared__ char smem[];
    const uint32_t sbase = smem_u32(smem);
    const int tid  = threadIdx.x;
    const int wid  = tid >> 5;
    const int lane = tid & 31;
    const int wm = wid >> 2;            // 0..1  (64-row slab)
    const int wn = wid & 3;             // 0..3  (32-col slab)
    const int block_row = blockIdx.x * 128;

    float acc[4][4][4];
#pragma unroll
    for (int i = 0; i < 4; ++i)
#pragma unroll
        for (int j = 0; j < 4; ++j)
#pragma unroll
            for (int k = 0; k < 4; ++k) acc[i][j][k] = 0.f;

    // ---- A: fp16 source, 4 slots of 16B (8 halves) per thread per chunk ----
    auto ldgA = [&](int kc, uint4* r) {
        const __half* a; int acol;
        if (kc < k1c) { a = a1f; acol = kc * KC; }
        else          { a = a2f; acol = (kc - k1c) * KC; }
#pragma unroll
        for (int t = 0; t < 4; ++t) {
            const int w = tid + t * 256;
            const int row = w >> 3;
            const int q = w & 7;
            uint4 v = make_uint4(0, 0, 0, 0);
            const int grow = block_row + row;
            if (grow < N_NODES)
                v = *(const uint4*)(a + (size_t)grow * 128 + acol + q * 8);
            r[t] = v;
        }
    };
    auto stsA = [&](int stage, const uint4* r) {
#pragma unroll
        for (int t = 0; t < 4; ++t) {
            const int w = tid + t * 256;
            const int row = w >> 3;
            const int q = w & 7;
            const __half2* hp = (const __half2*)&r[t];
            uint32_t hh[4], ll[4];
#pragma unroll
            for (int i = 0; i < 4; ++i) {
                float2 f = __half22float2(hp[i]);
                split2(f.x, f.y, hh[i], ll[i]);
            }
            char* base = smem + stage * STAGE_B + row * PITCH + q * 16;
            *(uint4*)base            = make_uint4(hh[0], hh[1], hh[2], hh[3]);
            *(uint4*)(base + TILE_B) = make_uint4(ll[0], ll[1], ll[2], ll[3]);
        }
    };
    // ---- B: bf16 pair source, 8 slots (4 hi + 4 lo) ----
    auto ldgB = [&](int kc, uint4* r) {
        const __nv_bfloat16 *bh, *bl; int acol;
        if (kc < k1c) { bh = b1h; bl = b1l; acol = kc * KC; }
        else          { bh = b2h; bl = b2l; acol = (kc - k1c) * KC; }
#pragma unroll
        for (int t = 0; t < 8; ++t) {
            const int which = t >> 2;
            const int w = tid + (t & 3) * 256;
            const int row = w >> 3;
            const int q = w & 7;
            const __nv_bfloat16* src = which ? bl : bh;
            r[t] = *(const uint4*)(src + (size_t)row * 128 + acol + q * 8);
        }
    };
    auto stsB = [&](int stage, const uint4* r) {
#pragma unroll
        for (int t = 0; t < 8; ++t) {
            const int which = t >> 2;
            const int w = tid + (t & 3) * 256;
            const int row = w >> 3;
            const int q = w & 7;
            *(uint4*)(smem + stage * STAGE_B + (2 + which) * TILE_B + row * PITCH + q * 16)
                = r[t];
        }
    };

    const int r8  = lane & 7;
    const int sub = lane >> 3;
    auto compute2 = [&](int stage, int ks0) {
        const uint32_t so = sbase + stage * STAGE_B;
        const uint32_t Ah = so;
        const uint32_t Al = so + TILE_B;
        const uint32_t Bh = so + 2 * TILE_B;
        const uint32_t Bl = so + 3 * TILE_B;
#pragma unroll
        for (int ks = ks0; ks < ks0 + 2; ++ks) {
            uint32_t ah[4][4], al[4][4], bh[4][2], bl[4][2];
#pragma unroll
            for (int mi = 0; mi < 4; ++mi) {
                const int arow = wm * 64 + mi * 16 + r8 + (sub & 1) * 8;
                const uint32_t addr = arow * PITCH + ks * 32 + (sub >> 1) * 16;
                ldm_x4(ah[mi][0], ah[mi][1], ah[mi][2], ah[mi][3], Ah + addr);
                ldm_x4(al[mi][0], al[mi][1], al[mi][2], al[mi][3], Al + addr);
            }
#pragma unroll
            for (int p = 0; p < 2; ++p) {
                const int nrow = wn * 32 + p * 16 + r8 + (sub >> 1) * 8;
                const uint32_t addr = nrow * PITCH + ks * 32 + (sub & 1) * 16;
                uint32_t r0, r1, r2, r3;
                ldm_x4(r0, r1, r2, r3, Bh + addr);
                bh[2 * p][0] = r0; bh[2 * p][1] = r1;
                bh[2 * p + 1][0] = r2; bh[2 * p + 1][1] = r3;
                ldm_x4(r0, r1, r2, r3, Bl + addr);
                bl[2 * p][0] = r0; bl[2 * p][1] = r1;
                bl[2 * p + 1][0] = r2; bl[2 * p + 1][1] = r3;
            }
#pragma unroll
            for (int mi = 0; mi < 4; ++mi)
#pragma unroll
                for (int nj = 0; nj < 4; ++nj) {
                    mma16816(acc[mi][nj], ah[mi], bh[nj]);
                    mma16816(acc[mi][nj], ah[mi], bl[nj]);
                    mma16816(acc[mi][nj], al[mi], bh[nj]);
                }
        }
    };

    // ---- prologue: chunk 0 into stage 0 ----
    {
        uint4 ra[4], rb[8];
        ldgA(0, ra); stsA(0, ra);
        ldgB(0, rb); stsB(0, rb);
    }

    // ---- main loop ----
    for (int kc = 0; kc < nc; ++kc) {
        const int cur = kc & 1;
        const int nxt = cur ^ 1;
        __syncthreads();
        const bool more = (kc + 1 < nc);
        {
            uint4 ra[4];
            if (more) ldgA(kc + 1, ra);
            compute2(cur, 0);
            if (more) stsA(nxt, ra);
        }
        {
            uint4 rb[8];
            if (more) ldgB(kc + 1, rb);
            compute2(cur, 2);
            if (more) stsB(nxt, rb);
        }
    }

    // ---- epilogue ----
    const int g = lane >> 2;
    const int tq = lane & 3;
    float* hs = (float*)smem;                 // fused-head staging (reuses stages)
    if (logits) __syncthreads();              // stage reads done before overwrite
#pragma unroll
    for (int nj = 0; nj < 4; ++nj) {
        const int col = wn * 32 + nj * 8 + 2 * tq;
        const float2 bb = *(const float2*)(bias + col);
#pragma unroll
        for (int mi = 0; mi < 4; ++mi) {
            const int row0 = block_row + wm * 64 + mi * 16 + g;
            const int row1 = row0 + 8;
            const int lr0 = wm * 64 + mi * 16 + g;
            const int lr1 = lr0 + 8;
            float d0 = fmaxf(acc[mi][nj][0] + bb.x, 0.f);
            float d1 = fmaxf(acc[mi][nj][1] + bb.y, 0.f);
            float d2 = fmaxf(acc[mi][nj][2] + bb.x, 0.f);
            float d3 = fmaxf(acc[mi][nj][3] + bb.y, 0.f);
            if (logits) {
                hs[lr0 * HPITCH + col]     = d0;
                hs[lr0 * HPITCH + col + 1] = d1;
                hs[lr1 * HPITCH + col]     = d2;
                hs[lr1 * HPITCH + col + 1] = d3;
            } else {
                if (row0 < N_NODES)
                    *(__half2*)(outh + (size_t)row0 * 128 + col) =
                        __float22half2_rn(make_float2(d0, d1));
                if (row1 < N_NODES)
                    *(__half2*)(outh + (size_t)row1 * 128 + col) =
                        __float22half2_rn(make_float2(d2, d3));
            }
        }
    }

    // ---- fused head2: logits = h @ Wc1 + bc1 (N_TRUCK=32) ----
    if (logits) {
        __syncthreads();
        const float bcv = __ldg(bc1 + lane);
#pragma unroll 1
        for (int rr = 0; rr < 16; ++rr) {
            const int lrow = wid * 16 + rr;
            const int grow = block_row + lrow;
            if (grow >= N_NODES) break;
            const float* hrow = hs + lrow * HPITCH;
            float a0 = bcv, a1 = 0.f, a2 = 0.f, a3 = 0.f;
#pragma unroll 8
            for (int k = 0; k < 128; k += 4) {
                a0 += hrow[k + 0] * __ldg(Wc1 + (k + 0) * N_TRUCK + lane);
                a1 += hrow[k + 1] * __ldg(Wc1 + (k + 1) * N_TRUCK + lane);
                a2 += hrow[k + 2] * __ldg(Wc1 + (k + 2) * N_TRUCK + lane);
                a3 += hrow[k + 3] * __ldg(Wc1 + (k + 3) * N_TRUCK + lane);
            }
            logits[(size_t)grow * N_TRUCK + lane] = a0 + a1 + a2 + a3;
        }
    }
}

// ---------------- launch ----------------------------------------------------
extern "C" void kernel_launch(void* const* d_in, const int* in_sizes, int n_in,
                              void* d_out, int out_size)
{
    const float* x      = (const float*)d_in[0];
    const int*   ei     = (const int*)d_in[1];
    const float* W_rel0 = (const float*)d_in[2];
    const float* b_rel0 = (const float*)d_in[3];
    const float* W_root0= (const float*)d_in[4];
    const float* W_rel1 = (const float*)d_in[5];
    const float* b_rel1 = (const float*)d_in[6];
    const float* W_root1= (const float*)d_in[7];
    const float* W_rel2 = (const float*)d_in[8];
    const float* b_rel2 = (const float*)d_in[9];
    const float* W_root2= (const float*)d_in[10];
    const float* Wc0    = (const float*)d_in[11];
    const float* bc0    = (const float*)d_in[12];
    const float* Wc1    = (const float*)d_in[13];
    const float* bc1    = (const float*)d_in[14];
    float* out = (float*)d_out;

    const int* srcp = ei;
    const int* dstp = ei + N_EDGES;

    __half *hx, *hA, *hB, *hC, *ag;
    __nv_bfloat16 *wtb;
    cudaGetSymbolAddress((void**)&hx,  g_hx);
    cudaGetSymbolAddress((void**)&hA,  g_hA);
    cudaGetSymbolAddress((void**)&hB,  g_hB);
    cudaGetSymbolAddress((void**)&hC,  g_hC);
    cudaGetSymbolAddress((void**)&ag,  g_ag);
    cudaGetSymbolAddress((void**)&wtb, g_wtb);

    cudaFuncSetAttribute(gemm_mma, cudaFuncAttributeMaxDynamicSharedMemorySize, GEMM_SMEM);

    const int nbScan = (N_NODES + 1023) / 1024;

    // CSR build (dst-sorted)
    zero_cnt_kernel<<<(N_NODES + 255) / 256, 256>>>();
    hist_kernel<<<(N_EDGES + 255) / 256, 256>>>(dstp);
    scan_phase1<<<nbScan, 1024>>>();
    scan_phase2<<<1, 128>>>(nbScan);
    scan_phase3<<<(N_NODES + 255) / 256, 256>>>();
    fill_kernel<<<(N_EDGES + 255) / 256, 256>>>(srcp, dstp);

    // prep: x -> fp16, transpose+split weights
    const int n4 = N_NODES * HIDC / 4;
    split_kernel<<<(n4 + 255) / 256, 256>>>(x, hx, n4);
    wprep_kernel<<<(7 * 16384 + 255) / 256, 256>>>(W_rel0, W_root0, W_rel1, W_root1,
                                                   W_rel2, W_root2, Wc0);

    const int aggGrid  = (N_NODES * 32 + 255) / 256;
    const int gemmGrid = (N_NODES + 127) / 128;
    __nv_bfloat16* wt = wtb;   // slot i at wt + i*16384

    // layer 0: agg(hx) -> ag ; gemm(A1=ag, A2=hx) -> hA
    agg_kernel<<<aggGrid, 256>>>(hx, ag);
    gemm_mma<<<gemmGrid, 256, GEMM_SMEM>>>(ag, hx,
        wt + 0*16384, wt + 1*16384, wt + 2*16384, wt + 3*16384,
        b_rel0, hA, nullptr, nullptr, nullptr, 4, 2);
    // layer 1: agg(hA) -> ag ; gemm(ag, hA) -> hB
    agg_kernel<<<aggGrid, 256>>>(hA, ag);
    gemm_mma<<<gemmGrid, 256, GEMM_SMEM>>>(ag, hA,
        wt + 4*16384, wt + 5*16384, wt + 6*16384, wt + 7*16384,
        b_rel1, hB, nullptr, nullptr, nullptr, 4, 2);
    // layer 2: agg(hB) -> ag ; gemm(ag, hB) -> hC
    agg_kernel<<<aggGrid, 256>>>(hB, ag);
    gemm_mma<<<gemmGrid, 256, GEMM_SMEM>>>(ag, hB,
        wt + 8*16384, wt + 9*16384, wt + 10*16384, wt + 11*16384,
        b_rel2, hC, nullptr, nullptr, nullptr, 4, 2);
    // head: hC @ Wc0 + bc0 -> relu -> @ Wc1 + bc1 -> logits (fused)
    gemm_mma<<<gemmGrid, 256, GEMM_SMEM>>>(nullptr, hC,
        nullptr, nullptr, wt + 12*16384, wt + 13*16384,
        bc0, nullptr, Wc1, bc1, out, 2, 0);
    (void)in_sizes; (void)n_in; (void)out_size;
}

// round 17
// speedup vs baseline: 1.7539x; 1.3741x over previous
#include <cuda_runtime.h>
#include <cuda_fp16.h>
#include <cstdint>
#include <cstddef>

#define N_NODES 100000
#define N_EDGES 1600000
#define HIDC    128
#define N_TRUCK 32

// ---------------- device scratch ------------------------------------------
__device__ __half g_hx  [(size_t)N_NODES * HIDC];   // fp16 x
__device__ __half g_hA  [(size_t)N_NODES * HIDC];   // fp16 h1
__device__ __half g_hB  [(size_t)N_NODES * HIDC];   // fp16 h2
__device__ __half g_hC  [(size_t)N_NODES * HIDC];   // fp16 h3
__device__ __half g_ag  [(size_t)N_NODES * HIDC];   // fp16 agg result
__device__ __half g_wt16[7 * 16384];                // transposed fp16 weights
__device__ int   g_cnt[N_NODES];
__device__ int   g_cursor[N_NODES];
__device__ int   g_rowptr[N_NODES + 1];
__device__ int   g_srcsorted[N_EDGES];
__device__ int   g_blocksums[128];

// ---------------- helpers ---------------------------------------------------
__device__ __forceinline__ uint32_t smem_u32(const void* p) {
    uint32_t a;
    asm("{ .reg .u64 t; cvta.to.shared.u64 t, %1; cvt.u32.u64 %0, t; }" : "=r"(a) : "l"(p));
    return a;
}
__device__ __forceinline__ void ldm_x4(uint32_t& r0, uint32_t& r1, uint32_t& r2,
                                       uint32_t& r3, uint32_t addr) {
    asm volatile("ldmatrix.sync.aligned.m8n8.x4.shared.b16 {%0,%1,%2,%3}, [%4];"
                 : "=r"(r0), "=r"(r1), "=r"(r2), "=r"(r3) : "r"(addr));
}
__device__ __forceinline__ void mma_f16(float* c, const uint32_t* a, const uint32_t* b) {
    asm volatile("mma.sync.aligned.m16n8k16.row.col.f32.f16.f16.f32 "
                 "{%0,%1,%2,%3}, {%4,%5,%6,%7}, {%8,%9}, {%0,%1,%2,%3};"
                 : "+f"(c[0]), "+f"(c[1]), "+f"(c[2]), "+f"(c[3])
                 : "r"(a[0]), "r"(a[1]), "r"(a[2]), "r"(a[3]), "r"(b[0]), "r"(b[1]));
}

// ---------------- CSR build ------------------------------------------------
__global__ void zero_cnt_kernel() {
    int i = blockIdx.x * blockDim.x + threadIdx.x;
    if (i < N_NODES) g_cnt[i] = 0;
}
__global__ void hist_kernel(const int* __restrict__ dst) {
    int i = blockIdx.x * blockDim.x + threadIdx.x;
    if (i < N_EDGES) atomicAdd(&g_cnt[dst[i]], 1);
}
__global__ void scan_phase1() {
    __shared__ int sh[1024];
    int i = blockIdx.x * 1024 + threadIdx.x;
    int v = (i < N_NODES) ? g_cnt[i] : 0;
    sh[threadIdx.x] = v;
    __syncthreads();
    for (int off = 1; off < 1024; off <<= 1) {
        int t = (threadIdx.x >= off) ? sh[threadIdx.x - off] : 0;
        __syncthreads();
        sh[threadIdx.x] += t;
        __syncthreads();
    }
    if (i < N_NODES) g_rowptr[i] = sh[threadIdx.x];
    if (threadIdx.x == 1023) g_blocksums[blockIdx.x] = sh[1023];
}
__global__ void scan_phase2(int nb) {
    __shared__ int sh[128];
    int t = threadIdx.x;
    int v = (t < nb) ? g_blocksums[t] : 0;
    sh[t] = v;
    __syncthreads();
    for (int off = 1; off < 128; off <<= 1) {
        int u = (t >= off) ? sh[t - off] : 0;
        __syncthreads();
        sh[t] += u;
        __syncthreads();
    }
    if (t < nb) g_blocksums[t] = sh[t] - v;   // exclusive
}
__global__ void scan_phase3() {
    int i = blockIdx.x * blockDim.x + threadIdx.x;
    if (i < N_NODES) {
        int excl = g_rowptr[i] - g_cnt[i] + g_blocksums[i >> 10];
        g_rowptr[i] = excl;
        g_cursor[i] = excl;
    }
    if (i == 0) g_rowptr[N_NODES] = N_EDGES;
}
__global__ void fill_kernel(const int* __restrict__ src, const int* __restrict__ dst) {
    int i = blockIdx.x * blockDim.x + threadIdx.x;
    if (i < N_EDGES) {
        int p = atomicAdd(&g_cursor[dst[i]], 1);
        g_srcsorted[p] = src[i];
    }
}

// ---------------- split x -> fp16 copy --------------------------------------
__global__ void split_kernel(const float* __restrict__ src,
                             __half* __restrict__ h16, int n4) {
    int i = blockIdx.x * blockDim.x + threadIdx.x;
    if (i >= n4) return;
    float4 v = __ldg((const float4*)src + i);
    __half2 p0 = __float22half2_rn(make_float2(v.x, v.y));
    __half2 p1 = __float22half2_rn(make_float2(v.z, v.w));
    *(uint2*)(h16 + (size_t)i * 4) =
        make_uint2(*reinterpret_cast<uint32_t*>(&p0), *reinterpret_cast<uint32_t*>(&p1));
}

// ---------------- weight prep: transpose to fp16 ----------------------------
__global__ void wprep_kernel(const float* __restrict__ w0, const float* __restrict__ w1,
                             const float* __restrict__ w2, const float* __restrict__ w3,
                             const float* __restrict__ w4, const float* __restrict__ w5,
                             const float* __restrict__ w6) {
    int gid = blockIdx.x * blockDim.x + threadIdx.x;
    if (gid >= 7 * 16384) return;
    int m = gid >> 14;
    int r = gid & 16383;
    int n = r >> 7;
    int k = r & 127;
    const float* W = (m == 0) ? w0 : (m == 1) ? w1 : (m == 2) ? w2 : (m == 3) ? w3
                   : (m == 4) ? w4 : (m == 5) ? w5 : w6;
    g_wt16[(size_t)m * 16384 + n * 128 + k] = __float2half(__ldg(W + k * 128 + n));
}

// ---------------- aggregation: warp per node, fp16 in, fp16 out ------------
__global__ void __launch_bounds__(256) agg_kernel(const __half* __restrict__ h,
                                                  __half* __restrict__ aout) {
    int gw   = (blockIdx.x * blockDim.x + threadIdx.x) >> 5;
    int lane = threadIdx.x & 31;
    if (gw >= N_NODES) return;
    int beg = g_rowptr[gw];
    int end = g_rowptr[gw + 1];
    float x0 = 0.f, x1 = 0.f, x2 = 0.f, x3 = 0.f;
    float y0 = 0.f, y1 = 0.f, y2 = 0.f, y3 = 0.f;
    int e = beg;
    for (; e + 2 <= end; e += 2) {
        int s0 = __ldg(g_srcsorted + e);
        int s1 = __ldg(g_srcsorted + e + 1);
        uint2 u0 = __ldg((const uint2*)(h + (size_t)s0 * HIDC + lane * 4));
        uint2 u1 = __ldg((const uint2*)(h + (size_t)s1 * HIDC + lane * 4));
        float2 f;
        f = __half22float2(*reinterpret_cast<__half2*>(&u0.x)); x0 += f.x; x1 += f.y;
        f = __half22float2(*reinterpret_cast<__half2*>(&u0.y)); x2 += f.x; x3 += f.y;
        f = __half22float2(*reinterpret_cast<__half2*>(&u1.x)); y0 += f.x; y1 += f.y;
        f = __half22float2(*reinterpret_cast<__half2*>(&u1.y)); y2 += f.x; y3 += f.y;
    }
    if (e < end) {
        int s0 = __ldg(g_srcsorted + e);
        uint2 u0 = __ldg((const uint2*)(h + (size_t)s0 * HIDC + lane * 4));
        float2 f;
        f = __half22float2(*reinterpret_cast<__half2*>(&u0.x)); x0 += f.x; x1 += f.y;
        f = __half22float2(*reinterpret_cast<__half2*>(&u0.y)); x2 += f.x; x3 += f.y;
    }
    x0 += y0; x1 += y1; x2 += y2; x3 += y3;
    __half2 o0 = __float22half2_rn(make_float2(x0, x1));
    __half2 o1 = __float22half2_rn(make_float2(x2, x3));
    *(uint2*)(aout + (size_t)gw * HIDC + lane * 4) =
        make_uint2(*reinterpret_cast<uint32_t*>(&o0), *reinterpret_cast<uint32_t*>(&o1));
}

// ---------------- native fp16 mma GEMM, 2 CTAs/SM --------------------------
// out = act( [A1|A2] @ [B1;B2] + bias ); A and B fp16; fp32 accumulate.
// Optional fused head2 via logits != null.
#define KC       64
#define PITCH    144                       // (64+8) halves * 2B, conflict-free ldmatrix
#define TILE_B   (128 * PITCH)             // 18432 B
#define STAGE_B  (2 * TILE_B)              // A, B = 36864 B
#define GEMM_SMEM (2 * STAGE_B)            // 73728 B -> 2 CTAs/SM
#define HPITCH   132                       // fp32 h row pitch (floats) for fused head

__global__ void __launch_bounds__(256, 2) gemm_mma(
    const __half* __restrict__ a1f, const __half* __restrict__ a2f,
    const __half* __restrict__ b1f, const __half* __restrict__ b2f,
    const float* __restrict__ bias,
    __half* __restrict__ outh,
    const float* __restrict__ Wc1, const float* __restrict__ bc1,
    float* __restrict__ logits,
    int nc, int k1c)
{
    extern __shared__ char smem[];
    const uint32_t sbase = smem_u32(smem);
    const int tid  = threadIdx.x;
    const int wid  = tid >> 5;
    const int lane = tid & 31;
    const int wm = wid >> 2;            // 0..1  (64-row slab)
    const int wn = wid & 3;             // 0..3  (32-col slab)
    const int block_row = blockIdx.x * 128;

    float acc[4][4][4];
#pragma unroll
    for (int i = 0; i < 4; ++i)
#pragma unroll
        for (int j = 0; j < 4; ++j)
#pragma unroll
            for (int k = 0; k < 4; ++k) acc[i][j][k] = 0.f;

    auto ldgA = [&](int kc, uint4* r) {
        const __half* a; int acol;
        if (kc < k1c) { a = a1f; acol = kc * KC; }
        else          { a = a2f; acol = (kc - k1c) * KC; }
#pragma unroll
        for (int t = 0; t < 4; ++t) {
            const int w = tid + t * 256;
            const int row = w >> 3;
            const int q = w & 7;
            uint4 v = make_uint4(0, 0, 0, 0);
            const int grow = block_row + row;
            if (grow < N_NODES)
                v = *(const uint4*)(a + (size_t)grow * 128 + acol + q * 8);
            r[t] = v;
        }
    };
    auto ldgB = [&](int kc, uint4* r) {
        const __half* b; int acol;
        if (kc < k1c) { b = b1f; acol = kc * KC; }
        else          { b = b2f; acol = (kc - k1c) * KC; }
#pragma unroll
        for (int t = 0; t < 4; ++t) {
            const int w = tid + t * 256;
            const int row = w >> 3;
            const int q = w & 7;
            r[t] = *(const uint4*)(b + (size_t)row * 128 + acol + q * 8);
        }
    };
    auto stsA = [&](int stage, const uint4* r) {
#pragma unroll
        for (int t = 0; t < 4; ++t) {
            const int w = tid + t * 256;
            const int row = w >> 3;
            const int q = w & 7;
            *(uint4*)(smem + stage * STAGE_B + row * PITCH + q * 16) = r[t];
        }
    };
    auto stsB = [&](int stage, const uint4* r) {
#pragma unroll
        for (int t = 0; t < 4; ++t) {
            const int w = tid + t * 256;
            const int row = w >> 3;
            const int q = w & 7;
            *(uint4*)(smem + stage * STAGE_B + TILE_B + row * PITCH + q * 16) = r[t];
        }
    };

    const int r8  = lane & 7;
    const int sub = lane >> 3;
    auto compute2 = [&](int stage, int ks0) {
        const uint32_t At = sbase + stage * STAGE_B;
        const uint32_t Bt = At + TILE_B;
#pragma unroll
        for (int ks = ks0; ks < ks0 + 2; ++ks) {
            uint32_t ah[4][4], bh[4][2];
#pragma unroll
            for (int mi = 0; mi < 4; ++mi) {
                const int arow = wm * 64 + mi * 16 + r8 + (sub & 1) * 8;
                const uint32_t addr = arow * PITCH + ks * 32 + (sub >> 1) * 16;
                ldm_x4(ah[mi][0], ah[mi][1], ah[mi][2], ah[mi][3], At + addr);
            }
#pragma unroll
            for (int p = 0; p < 2; ++p) {
                const int nrow = wn * 32 + p * 16 + r8 + (sub >> 1) * 8;
                const uint32_t addr = nrow * PITCH + ks * 32 + (sub & 1) * 16;
                uint32_t r0, r1, r2, r3;
                ldm_x4(r0, r1, r2, r3, Bt + addr);
                bh[2 * p][0] = r0; bh[2 * p][1] = r1;
                bh[2 * p + 1][0] = r2; bh[2 * p + 1][1] = r3;
            }
#pragma unroll
            for (int mi = 0; mi < 4; ++mi)
#pragma unroll
                for (int nj = 0; nj < 4; ++nj)
                    mma_f16(acc[mi][nj], ah[mi], bh[nj]);
        }
    };

    // ---- prologue: chunk 0 into stage 0 ----
    {
        uint4 ra[4], rb[4];
        ldgA(0, ra); stsA(0, ra);
        ldgB(0, rb); stsB(0, rb);
    }

    // ---- main loop ----
    for (int kc = 0; kc < nc; ++kc) {
        const int cur = kc & 1;
        const int nxt = cur ^ 1;
        __syncthreads();
        const bool more = (kc + 1 < nc);
        {
            uint4 ra[4];
            if (more) ldgA(kc + 1, ra);
            compute2(cur, 0);
            if (more) stsA(nxt, ra);
        }
        {
            uint4 rb[4];
            if (more) ldgB(kc + 1, rb);
            compute2(cur, 2);
            if (more) stsB(nxt, rb);
        }
    }

    // ---- epilogue ----
    const int g = lane >> 2;
    const int tq = lane & 3;
    float* hs = (float*)smem;                 // fused-head staging (reuses stages)
    if (logits) __syncthreads();              // stage reads done before overwrite
#pragma unroll
    for (int nj = 0; nj < 4; ++nj) {
        const int col = wn * 32 + nj * 8 + 2 * tq;
        const float2 bb = *(const float2*)(bias + col);
#pragma unroll
        for (int mi = 0; mi < 4; ++mi) {
            const int row0 = block_row + wm * 64 + mi * 16 + g;
            const int row1 = row0 + 8;
            const int lr0 = wm * 64 + mi * 16 + g;
            const int lr1 = lr0 + 8;
            float d0 = fmaxf(acc[mi][nj][0] + bb.x, 0.f);
            float d1 = fmaxf(acc[mi][nj][1] + bb.y, 0.f);
            float d2 = fmaxf(acc[mi][nj][2] + bb.x, 0.f);
            float d3 = fmaxf(acc[mi][nj][3] + bb.y, 0.f);
            if (logits) {
                hs[lr0 * HPITCH + col]     = d0;
                hs[lr0 * HPITCH + col + 1] = d1;
                hs[lr1 * HPITCH + col]     = d2;
                hs[lr1 * HPITCH + col + 1] = d3;
            } else {
                if (row0 < N_NODES)
                    *(__half2*)(outh + (size_t)row0 * 128 + col) =
                        __float22half2_rn(make_float2(d0, d1));
                if (row1 < N_NODES)
                    *(__half2*)(outh + (size_t)row1 * 128 + col) =
                        __float22half2_rn(make_float2(d2, d3));
            }
        }
    }

    // ---- fused head2: logits = h @ Wc1 + bc1 (N_TRUCK=32) ----
    if (logits) {
        __syncthreads();
        const float bcv = __ldg(bc1 + lane);
#pragma unroll 1
        for (int rr = 0; rr < 16; ++rr) {
            const int lrow = wid * 16 + rr;
            const int grow = block_row + lrow;
            if (grow >= N_NODES) break;
            const float* hrow = hs + lrow * HPITCH;
            float a0 = bcv, a1 = 0.f, a2 = 0.f, a3 = 0.f;
#pragma unroll 8
            for (int k = 0; k < 128; k += 4) {
                a0 += hrow[k + 0] * __ldg(Wc1 + (k + 0) * N_TRUCK + lane);
                a1 += hrow[k + 1] * __ldg(Wc1 + (k + 1) * N_TRUCK + lane);
                a2 += hrow[k + 2] * __ldg(Wc1 + (k + 2) * N_TRUCK + lane);
                a3 += hrow[k + 3] * __ldg(Wc1 + (k + 3) * N_TRUCK + lane);
            }
            logits[(size_t)grow * N_TRUCK + lane] = a0 + a1 + a2 + a3;
        }
    }
}

// ---------------- launch ----------------------------------------------------
extern "C" void kernel_launch(void* const* d_in, const int* in_sizes, int n_in,
                              void* d_out, int out_size)
{
    const float* x      = (const float*)d_in[0];
    const int*   ei     = (const int*)d_in[1];
    const float* W_rel0 = (const float*)d_in[2];
    const float* b_rel0 = (const float*)d_in[3];
    const float* W_root0= (const float*)d_in[4];
    const float* W_rel1 = (const float*)d_in[5];
    const float* b_rel1 = (const float*)d_in[6];
    const float* W_root1= (const float*)d_in[7];
    const float* W_rel2 = (const float*)d_in[8];
    const float* b_rel2 = (const float*)d_in[9];
    const float* W_root2= (const float*)d_in[10];
    const float* Wc0    = (const float*)d_in[11];
    const float* bc0    = (const float*)d_in[12];
    const float* Wc1    = (const float*)d_in[13];
    const float* bc1    = (const float*)d_in[14];
    float* out = (float*)d_out;

    const int* srcp = ei;
    const int* dstp = ei + N_EDGES;

    __half *hx, *hA, *hB, *hC, *ag, *wt;
    cudaGetSymbolAddress((void**)&hx,  g_hx);
    cudaGetSymbolAddress((void**)&hA,  g_hA);
    cudaGetSymbolAddress((void**)&hB,  g_hB);
    cudaGetSymbolAddress((void**)&hC,  g_hC);
    cudaGetSymbolAddress((void**)&ag,  g_ag);
    cudaGetSymbolAddress((void**)&wt,  g_wt16);

    cudaFuncSetAttribute(gemm_mma, cudaFuncAttributeMaxDynamicSharedMemorySize, GEMM_SMEM);

    const int nbScan = (N_NODES + 1023) / 1024;

    // CSR build (dst-sorted)
    zero_cnt_kernel<<<(N_NODES + 255) / 256, 256>>>();
    hist_kernel<<<(N_EDGES + 255) / 256, 256>>>(dstp);
    scan_phase1<<<nbScan, 1024>>>();
    scan_phase2<<<1, 128>>>(nbScan);
    scan_phase3<<<(N_NODES + 255) / 256, 256>>>();
    fill_kernel<<<(N_EDGES + 255) / 256, 256>>>(srcp, dstp);

    // prep: x -> fp16, transpose weights -> fp16
    const int n4 = N_NODES * HIDC / 4;
    split_kernel<<<(n4 + 255) / 256, 256>>>(x, hx, n4);
    wprep_kernel<<<(7 * 16384 + 255) / 256, 256>>>(W_rel0, W_root0, W_rel1, W_root1,
                                                   W_rel2, W_root2, Wc0);

    const int aggGrid  = (N_NODES * 32 + 255) / 256;
    const int gemmGrid = (N_NODES + 127) / 128;
    // weight slots: 0 rel0, 1 root0, 2 rel1, 3 root1, 4 rel2, 5 root2, 6 Wc0

    // layer 0: agg(hx) -> ag ; gemm(A1=ag@rel0, A2=hx@root0) -> hA
    agg_kernel<<<aggGrid, 256>>>(hx, ag);
    gemm_mma<<<gemmGrid, 256, GEMM_SMEM>>>(ag, hx,
        wt + 0*16384, wt + 1*16384, b_rel0, hA, nullptr, nullptr, nullptr, 4, 2);
    // layer 1
    agg_kernel<<<aggGrid, 256>>>(hA, ag);
    gemm_mma<<<gemmGrid, 256, GEMM_SMEM>>>(ag, hA,
        wt + 2*16384, wt + 3*16384, b_rel1, hB, nullptr, nullptr, nullptr, 4, 2);
    // layer 2
    agg_kernel<<<aggGrid, 256>>>(hB, ag);
    gemm_mma<<<gemmGrid, 256, GEMM_SMEM>>>(ag, hB,
        wt + 4*16384, wt + 5*16384, b_rel2, hC, nullptr, nullptr, nullptr, 4, 2);
    // head: hC @ Wc0 + bc0 -> relu -> @ Wc1 + bc1 -> logits (fused)
    gemm_mma<<<gemmGrid, 256, GEMM_SMEM>>>(nullptr, hC,
        nullptr, wt + 6*16384, bc0, nullptr, Wc1, bc1, out, 2, 0);
    (void)in_sizes; (void)n_in; (void)out_size;
}